// round 1
// baseline (speedup 1.0000x reference)
#include <cuda_runtime.h>
#include <math.h>

// Problem constants
#define BB 4
#define CC 512
#define CQd 128      // C/4
#define NN 4096      // H*W

// ---------------------------------------------------------------------------
// Scratch (device globals — allocation-free per harness rules)
// ---------------------------------------------------------------------------
__device__ float g_q[BB * CQd * NN];                 // 8 MB   [B, CQ, N]
__device__ float g_k[BB * CQd * NN];                 // 8 MB   [B, CQ, N]
__device__ float g_v[BB * CC  * NN];                 // 32 MB  [B, C,  N]
__device__ float g_P[(size_t)BB * NN * NN];          // 256 MB [B, N, N]

// ---------------------------------------------------------------------------
// Generic 128x128x8 fp32 tiled GEMM, 256 threads, 8x8 micro-tile per thread.
//
//   TRA = false : A stored K-major  (As[kk][m] = A[(k0+kk)*lda + m0+m])
//   TRA = true  : A stored M-major  (As[kk][m] = A[(m0+m)*lda + k0+kk])
//   (same for B / n)
//
//   EPI = 0 : C = scale * acc
//   EPI = 1 : C = gamma[0] * acc + add      (residual epilogue)
//
// All dims assumed multiples of tile sizes (true for this problem).
// ---------------------------------------------------------------------------
template <bool TRA, bool TRB, int EPI>
__global__ __launch_bounds__(256, 2)
void gemm128(const float* __restrict__ A, const float* __restrict__ Bm,
             float* __restrict__ C, const float* __restrict__ add,
             const float* __restrict__ gammap,
             int K, int lda, int ldb, int ldc,
             long sA, long sB, long sC,
             float scale)
{
    __shared__ float As[8][128];
    __shared__ float Bs[8][128];

    const int b  = blockIdx.z;
    const float* Ab = A  + (long)b * sA;
    const float* Bb = Bm + (long)b * sB;
    float*       Cb = C  + (long)b * sC;

    const int m0 = blockIdx.y * 128;
    const int n0 = blockIdx.x * 128;
    const int tid = threadIdx.x;
    const int tm = (tid >> 4) * 8;   // 0..120
    const int tn = (tid & 15) * 8;   // 0..120

    float acc[8][8];
    #pragma unroll
    for (int i = 0; i < 8; i++)
        #pragma unroll
        for (int j = 0; j < 8; j++) acc[i][j] = 0.0f;

    for (int k0 = 0; k0 < K; k0 += 8) {
        // ---- load A tile ----
        if (TRA) {
            int m  = tid >> 1;
            int kk = (tid & 1) * 4;
            float4 v = *(const float4*)&Ab[(long)(m0 + m) * lda + k0 + kk];
            As[kk + 0][m] = v.x; As[kk + 1][m] = v.y;
            As[kk + 2][m] = v.z; As[kk + 3][m] = v.w;
        } else {
            int kk = tid >> 5;
            int c  = (tid & 31) * 4;
            *(float4*)&As[kk][c] = *(const float4*)&Ab[(long)(k0 + kk) * lda + m0 + c];
        }
        // ---- load B tile ----
        if (TRB) {
            int n  = tid >> 1;
            int kk = (tid & 1) * 4;
            float4 v = *(const float4*)&Bb[(long)(n0 + n) * ldb + k0 + kk];
            Bs[kk + 0][n] = v.x; Bs[kk + 1][n] = v.y;
            Bs[kk + 2][n] = v.z; Bs[kk + 3][n] = v.w;
        } else {
            int kk = tid >> 5;
            int c  = (tid & 31) * 4;
            *(float4*)&Bs[kk][c] = *(const float4*)&Bb[(long)(k0 + kk) * ldb + n0 + c];
        }
        __syncthreads();

        #pragma unroll
        for (int kk = 0; kk < 8; kk++) {
            float4 a0 = *(const float4*)&As[kk][tm];
            float4 a1 = *(const float4*)&As[kk][tm + 4];
            float4 b0 = *(const float4*)&Bs[kk][tn];
            float4 b1 = *(const float4*)&Bs[kk][tn + 4];
            float a[8] = {a0.x, a0.y, a0.z, a0.w, a1.x, a1.y, a1.z, a1.w};
            float bv[8] = {b0.x, b0.y, b0.z, b0.w, b1.x, b1.y, b1.z, b1.w};
            #pragma unroll
            for (int i = 0; i < 8; i++)
                #pragma unroll
                for (int j = 0; j < 8; j++)
                    acc[i][j] = fmaf(a[i], bv[j], acc[i][j]);
        }
        __syncthreads();
    }

    // ---- epilogue ----
    if (EPI == 0) {
        #pragma unroll
        for (int i = 0; i < 8; i++) {
            float* cp = Cb + (long)(m0 + tm + i) * ldc + n0 + tn;
            #pragma unroll
            for (int j = 0; j < 8; j += 4) {
                float4 v;
                v.x = scale * acc[i][j + 0];
                v.y = scale * acc[i][j + 1];
                v.z = scale * acc[i][j + 2];
                v.w = scale * acc[i][j + 3];
                *(float4*)&cp[j] = v;
            }
        }
    } else {
        const float g = gammap[0];
        const float* addb = add + (long)b * sC;
        #pragma unroll
        for (int i = 0; i < 8; i++) {
            long off = (long)(m0 + tm + i) * ldc + n0 + tn;
            float* cp = Cb + off;
            const float* ap = addb + off;
            #pragma unroll
            for (int j = 0; j < 8; j += 4) {
                float4 r = *(const float4*)&ap[j];
                float4 v;
                v.x = fmaf(g, acc[i][j + 0], r.x);
                v.y = fmaf(g, acc[i][j + 1], r.y);
                v.z = fmaf(g, acc[i][j + 2], r.z);
                v.w = fmaf(g, acc[i][j + 3], r.w);
                *(float4*)&cp[j] = v;
            }
        }
    }
}

// ---------------------------------------------------------------------------
// Row softmax over 4096 elements, one block (256 threads) per row, in place.
// ---------------------------------------------------------------------------
__global__ __launch_bounds__(256)
void softmax_rows(float* __restrict__ P)
{
    __shared__ float buf[NN];
    __shared__ float red[8];

    const long row = blockIdx.x;
    float* p = P + row * (long)NN;
    const int tid = threadIdx.x;

    // pass 1: load + max
    float mx = -1e30f;
    for (int i = tid; i < NN; i += 256) {
        float v = p[i];
        buf[i] = v;
        mx = fmaxf(mx, v);
    }
    #pragma unroll
    for (int o = 16; o; o >>= 1) mx = fmaxf(mx, __shfl_xor_sync(0xffffffffu, mx, o));
    if ((tid & 31) == 0) red[tid >> 5] = mx;
    __syncthreads();
    if (tid == 0) {
        float v = red[0];
        #pragma unroll
        for (int i = 1; i < 8; i++) v = fmaxf(v, red[i]);
        red[0] = v;
    }
    __syncthreads();
    mx = red[0];
    __syncthreads();

    // pass 2: exp + sum
    float s = 0.0f;
    for (int i = tid; i < NN; i += 256) {
        float e = __expf(buf[i] - mx);
        buf[i] = e;
        s += e;
    }
    #pragma unroll
    for (int o = 16; o; o >>= 1) s += __shfl_xor_sync(0xffffffffu, s, o);
    if ((tid & 31) == 0) red[tid >> 5] = s;
    __syncthreads();
    if (tid == 0) {
        float v = 0.0f;
        #pragma unroll
        for (int i = 0; i < 8; i++) v += red[i];
        red[0] = v;
    }
    __syncthreads();
    const float inv = 1.0f / red[0];

    // pass 3: normalize + store
    for (int i = tid; i < NN; i += 256) p[i] = buf[i] * inv;
}

// ---------------------------------------------------------------------------
// Launcher
// ---------------------------------------------------------------------------
extern "C" void kernel_launch(void* const* d_in, const int* in_sizes, int n_in,
                              void* d_out, int out_size)
{
    const float* vt    = (const float*)d_in[0];
    const float* vs    = (const float*)d_in[1];
    const float* Wq    = (const float*)d_in[2];
    const float* Wk    = (const float*)d_in[3];
    const float* Wv    = (const float*)d_in[4];
    const float* gamma = (const float*)d_in[5];
    float* out = (float*)d_out;

    float* qp; float* kp; float* vp; float* Pp;
    cudaGetSymbolAddress((void**)&qp, g_q);
    cudaGetSymbolAddress((void**)&kp, g_k);
    cudaGetSymbolAddress((void**)&vp, g_v);
    cudaGetSymbolAddress((void**)&Pp, g_P);

    const float eq_scale   = 1.0f / sqrtf((float)CC);   // 1/sqrt(512)
    const float attn_scale = 1.0f / sqrtf((float)CC);

    // 1) projections: out[o,n] = eq * sum_c W[o,c] * x[b,c,n]
    //    A = W [M,K] (trans load), B = x [K,N] (direct), K=512
    gemm128<true, false, 0><<<dim3(NN / 128, CQd / 128, BB), 256>>>(
        Wq, vt, qp, nullptr, nullptr,
        CC, CC, NN, NN,
        0, (long)CC * NN, (long)CQd * NN, eq_scale);

    gemm128<true, false, 0><<<dim3(NN / 128, CQd / 128, BB), 256>>>(
        Wk, vs, kp, nullptr, nullptr,
        CC, CC, NN, NN,
        0, (long)CC * NN, (long)CQd * NN, eq_scale);

    gemm128<true, false, 0><<<dim3(NN / 128, CC / 128, BB), 256>>>(
        Wv, vs, vp, nullptr, nullptr,
        CC, CC, NN, NN,
        0, (long)CC * NN, (long)CC * NN, eq_scale);

    // 2) energy: E[n,m] = attn_scale * sum_o q[o,n] * k[o,m]
    //    A = q [K=CQ, M=N] direct, B = k [K=CQ, N] direct
    gemm128<false, false, 0><<<dim3(NN / 128, NN / 128, BB), 256>>>(
        qp, kp, Pp, nullptr, nullptr,
        CQd, NN, NN, NN,
        (long)CQd * NN, (long)CQd * NN, (long)NN * NN, attn_scale);

    // 3) softmax rows (in place on g_P)
    softmax_rows<<<BB * NN, 256>>>(Pp);

    // 4) PV + residual: out[c,n] = gamma * sum_m v[c,m] * P[n,m] + vt[c,n]
    //    A = v [M=C, K=N] trans, B = P [N, K=N] trans
    gemm128<true, true, 1><<<dim3(NN / 128, CC / 128, BB), 256>>>(
        vp, Pp, out, vt, gamma,
        NN, NN, NN, NN,
        (long)CC * NN, (long)NN * NN, (long)CC * NN, 1.0f);
}

// round 2
// speedup vs baseline: 2.8931x; 2.8931x over previous
#include <cuda_runtime.h>
#include <math.h>
#include <stdint.h>

// Problem constants
#define BB 4
#define CC 512
#define CQd 128      // C/4
#define NN 4096      // H*W

// ---------------------------------------------------------------------------
// Scratch (device globals — allocation-free per harness rules)
// ---------------------------------------------------------------------------
__device__ float g_q[BB * CQd * NN];                 // 8 MB   [B, CQ, N]
__device__ float g_k[BB * CQd * NN];                 // 8 MB   [B, CQ, N]
__device__ float g_v[BB * CC  * NN];                 // 32 MB  [B, C,  N]
__device__ float g_P[(size_t)BB * NN * NN];          // 256 MB [B, N, N]

__device__ __forceinline__ uint32_t f2tf32(float f) {
    uint32_t r;
    asm("cvt.rna.tf32.f32 %0, %1;" : "=r"(r) : "f"(f));
    return r;
}

// ---------------------------------------------------------------------------
// tf32 tensor-core GEMM, 128x128 block tile, BK=32, 256 threads (8 warps).
// Warp grid 2(m) x 4(n): each warp owns 64x32, built from m16n8k8 mma tiles.
//
//   TA = true  : A stored row-major [M][K]  -> smem layout T: [row][BK+4]
//   TA = false : A stored K-major  [K][M]  -> smem layout N: [BK][128+8]
//   (same for B / N dim)
//
//   EPI = 0 : C = scale * acc
//   EPI = 1 : C = gamma[0] * acc + add      (residual epilogue)
//
// All dims multiples of tile sizes (true here).
// ---------------------------------------------------------------------------
#define LTS 36    // T-layout row stride (floats): BK + 4
#define LNS 136   // N-layout row stride (floats): 128 + 8

template <bool TA, bool TB, int EPI>
__global__ __launch_bounds__(256)
void gemm_tc(const float* __restrict__ A, const float* __restrict__ Bm,
             float* __restrict__ C, const float* __restrict__ add,
             const float* __restrict__ gammap,
             int K, int lda, int ldb, int ldc,
             long sA, long sB, long sC,
             float scale)
{
    __shared__ uint32_t As[TA ? 128 * LTS : 32 * LNS];
    __shared__ uint32_t Bs[TB ? 128 * LTS : 32 * LNS];

    const int b  = blockIdx.z;
    const float* Ab = A  + (long)b * sA;
    const float* Bb = Bm + (long)b * sB;

    const int m0 = blockIdx.y * 128;
    const int n0 = blockIdx.x * 128;
    const int tid  = threadIdx.x;
    const int lane = tid & 31;
    const int warp = tid >> 5;
    const int wm = (warp >> 2) * 64;   // warp m offset: 0 or 64
    const int wn = (warp & 3) * 32;    // warp n offset: 0..96
    const int g  = lane >> 2;          // group id 0..7
    const int tg = lane & 3;           // thread-in-group 0..3

    float acc[4][4][4];
    #pragma unroll
    for (int mi = 0; mi < 4; mi++)
        #pragma unroll
        for (int ni = 0; ni < 4; ni++)
            #pragma unroll
            for (int r = 0; r < 4; r++) acc[mi][ni][r] = 0.0f;

    for (int k0 = 0; k0 < K; k0 += 32) {
        // ---- load A tile ----
        if (TA) {
            #pragma unroll
            for (int i = 0; i < 4; i++) {
                int l = tid + 256 * i;
                int r = l >> 3, k4 = (l & 7) << 2;
                float4 v = *(const float4*)&Ab[(long)(m0 + r) * lda + k0 + k4];
                uint32_t* d = &As[r * LTS + k4];
                d[0] = f2tf32(v.x); d[1] = f2tf32(v.y);
                d[2] = f2tf32(v.z); d[3] = f2tf32(v.w);
            }
        } else {
            #pragma unroll
            for (int i = 0; i < 4; i++) {
                int l = tid + 256 * i;
                int k = l >> 5, c4 = (l & 31) << 2;
                float4 v = *(const float4*)&Ab[(long)(k0 + k) * lda + m0 + c4];
                uint32_t* d = &As[k * LNS + c4];
                d[0] = f2tf32(v.x); d[1] = f2tf32(v.y);
                d[2] = f2tf32(v.z); d[3] = f2tf32(v.w);
            }
        }
        // ---- load B tile ----
        if (TB) {
            #pragma unroll
            for (int i = 0; i < 4; i++) {
                int l = tid + 256 * i;
                int r = l >> 3, k4 = (l & 7) << 2;
                float4 v = *(const float4*)&Bb[(long)(n0 + r) * ldb + k0 + k4];
                uint32_t* d = &Bs[r * LTS + k4];
                d[0] = f2tf32(v.x); d[1] = f2tf32(v.y);
                d[2] = f2tf32(v.z); d[3] = f2tf32(v.w);
            }
        } else {
            #pragma unroll
            for (int i = 0; i < 4; i++) {
                int l = tid + 256 * i;
                int k = l >> 5, c4 = (l & 31) << 2;
                float4 v = *(const float4*)&Bb[(long)(k0 + k) * ldb + n0 + c4];
                uint32_t* d = &Bs[k * LNS + c4];
                d[0] = f2tf32(v.x); d[1] = f2tf32(v.y);
                d[2] = f2tf32(v.z); d[3] = f2tf32(v.w);
            }
        }
        __syncthreads();

        #pragma unroll
        for (int ks = 0; ks < 4; ks++) {
            const int k8 = ks * 8;
            // B fragments for the 4 n-tiles
            uint32_t bf[4][2];
            #pragma unroll
            for (int ni = 0; ni < 4; ni++) {
                const int n = wn + ni * 8 + g;
                if (TB) {
                    bf[ni][0] = Bs[n * LTS + k8 + tg];
                    bf[ni][1] = Bs[n * LTS + k8 + tg + 4];
                } else {
                    bf[ni][0] = Bs[(k8 + tg) * LNS + n];
                    bf[ni][1] = Bs[(k8 + tg + 4) * LNS + n];
                }
            }
            #pragma unroll
            for (int mi = 0; mi < 4; mi++) {
                uint32_t af[4];
                const int m = wm + mi * 16 + g;
                if (TA) {
                    af[0] = As[m * LTS + k8 + tg];
                    af[1] = As[(m + 8) * LTS + k8 + tg];
                    af[2] = As[m * LTS + k8 + tg + 4];
                    af[3] = As[(m + 8) * LTS + k8 + tg + 4];
                } else {
                    af[0] = As[(k8 + tg) * LNS + m];
                    af[1] = As[(k8 + tg) * LNS + m + 8];
                    af[2] = As[(k8 + tg + 4) * LNS + m];
                    af[3] = As[(k8 + tg + 4) * LNS + m + 8];
                }
                #pragma unroll
                for (int ni = 0; ni < 4; ni++) {
                    asm volatile(
                        "mma.sync.aligned.m16n8k8.row.col.f32.tf32.tf32.f32 "
                        "{%0,%1,%2,%3}, {%4,%5,%6,%7}, {%8,%9}, {%0,%1,%2,%3};"
                        : "+f"(acc[mi][ni][0]), "+f"(acc[mi][ni][1]),
                          "+f"(acc[mi][ni][2]), "+f"(acc[mi][ni][3])
                        : "r"(af[0]), "r"(af[1]), "r"(af[2]), "r"(af[3]),
                          "r"(bf[ni][0]), "r"(bf[ni][1]));
                }
            }
        }
        __syncthreads();
    }

    // ---- epilogue ----
    float* Cb = C + (long)b * sC;
    const float gm = (EPI == 1) ? gammap[0] : 0.0f;
    const float* addb = (EPI == 1) ? (add + (long)b * sC) : nullptr;

    #pragma unroll
    for (int mi = 0; mi < 4; mi++) {
        #pragma unroll
        for (int half = 0; half < 2; half++) {
            const int row = m0 + wm + mi * 16 + g + half * 8;
            #pragma unroll
            for (int ni = 0; ni < 4; ni++) {
                const int col = n0 + wn + ni * 8 + 2 * tg;
                const long off = (long)row * ldc + col;
                float c0 = acc[mi][ni][half * 2 + 0];
                float c1 = acc[mi][ni][half * 2 + 1];
                if (EPI == 0) {
                    float2 v; v.x = scale * c0; v.y = scale * c1;
                    *(float2*)&Cb[off] = v;
                } else {
                    float2 r = *(const float2*)&addb[off];
                    float2 v;
                    v.x = fmaf(gm, c0, r.x);
                    v.y = fmaf(gm, c1, r.y);
                    *(float2*)&Cb[off] = v;
                }
            }
        }
    }
}

// ---------------------------------------------------------------------------
// Row softmax over 4096 elements, one block (256 threads) per row, in place.
// ---------------------------------------------------------------------------
__global__ __launch_bounds__(256)
void softmax_rows(float* __restrict__ P)
{
    __shared__ float buf[NN];
    __shared__ float red[8];

    const long row = blockIdx.x;
    float* p = P + row * (long)NN;
    const int tid = threadIdx.x;

    float mx = -1e30f;
    for (int i = tid; i < NN; i += 256) {
        float v = p[i];
        buf[i] = v;
        mx = fmaxf(mx, v);
    }
    #pragma unroll
    for (int o = 16; o; o >>= 1) mx = fmaxf(mx, __shfl_xor_sync(0xffffffffu, mx, o));
    if ((tid & 31) == 0) red[tid >> 5] = mx;
    __syncthreads();
    if (tid == 0) {
        float v = red[0];
        #pragma unroll
        for (int i = 1; i < 8; i++) v = fmaxf(v, red[i]);
        red[0] = v;
    }
    __syncthreads();
    mx = red[0];
    __syncthreads();

    float s = 0.0f;
    for (int i = tid; i < NN; i += 256) {
        float e = __expf(buf[i] - mx);
        buf[i] = e;
        s += e;
    }
    #pragma unroll
    for (int o = 16; o; o >>= 1) s += __shfl_xor_sync(0xffffffffu, s, o);
    if ((tid & 31) == 0) red[tid >> 5] = s;
    __syncthreads();
    if (tid == 0) {
        float v = 0.0f;
        #pragma unroll
        for (int i = 0; i < 8; i++) v += red[i];
        red[0] = v;
    }
    __syncthreads();
    const float inv = 1.0f / red[0];

    for (int i = tid; i < NN; i += 256) p[i] = buf[i] * inv;
}

// ---------------------------------------------------------------------------
// Launcher
// ---------------------------------------------------------------------------
extern "C" void kernel_launch(void* const* d_in, const int* in_sizes, int n_in,
                              void* d_out, int out_size)
{
    const float* vt    = (const float*)d_in[0];
    const float* vs    = (const float*)d_in[1];
    const float* Wq    = (const float*)d_in[2];
    const float* Wk    = (const float*)d_in[3];
    const float* Wv    = (const float*)d_in[4];
    const float* gamma = (const float*)d_in[5];
    float* out = (float*)d_out;

    float* qp; float* kp; float* vp; float* Pp;
    cudaGetSymbolAddress((void**)&qp, g_q);
    cudaGetSymbolAddress((void**)&kp, g_k);
    cudaGetSymbolAddress((void**)&vp, g_v);
    cudaGetSymbolAddress((void**)&Pp, g_P);

    const float eq_scale   = 1.0f / sqrtf((float)CC);
    const float attn_scale = 1.0f / sqrtf((float)CC);

    // 1) projections: q/k/v[o,n] = eq * sum_c W[o,c] * x[b,c,n]
    //    A = W [M][K] row-major (TA), B = x [K][N] (direct), K=512
    gemm_tc<true, false, 0><<<dim3(NN / 128, CQd / 128, BB), 256>>>(
        Wq, vt, qp, nullptr, nullptr,
        CC, CC, NN, NN,
        0, (long)CC * NN, (long)CQd * NN, eq_scale);

    gemm_tc<true, false, 0><<<dim3(NN / 128, CQd / 128, BB), 256>>>(
        Wk, vs, kp, nullptr, nullptr,
        CC, CC, NN, NN,
        0, (long)CC * NN, (long)CQd * NN, eq_scale);

    gemm_tc<true, false, 0><<<dim3(NN / 128, CC / 128, BB), 256>>>(
        Wv, vs, vp, nullptr, nullptr,
        CC, CC, NN, NN,
        0, (long)CC * NN, (long)CC * NN, eq_scale);

    // 2) energy: E[n,m] = attn_scale * sum_o q[o,n] * k[o,m]
    //    A = q [K][M] direct, B = k [K][N] direct, K=CQ=128
    gemm_tc<false, false, 0><<<dim3(NN / 128, NN / 128, BB), 256>>>(
        qp, kp, Pp, nullptr, nullptr,
        CQd, NN, NN, NN,
        (long)CQd * NN, (long)CQd * NN, (long)NN * NN, attn_scale);

    // 3) softmax rows (in place on g_P)
    softmax_rows<<<BB * NN, 256>>>(Pp);

    // 4) PV + residual: out[c,n] = gamma * sum_m v[c,m] * P[n,m] + vt[c,n]
    //    A = v [M][K] row-major (TA), B = P [N][K] row-major (TB), K=N=4096
    gemm_tc<true, true, 1><<<dim3(NN / 128, CC / 128, BB), 256>>>(
        vp, Pp, out, vt, gamma,
        NN, NN, NN, NN,
        (long)CC * NN, (long)NN * NN, (long)CC * NN, 1.0f);
}

// round 3
// speedup vs baseline: 5.0103x; 1.7318x over previous
#include <cuda_runtime.h>
#include <cuda_bf16.h>
#include <math.h>
#include <stdint.h>

#define BB 4
#define CC 512
#define CQd 128      // C/4
#define NN 4096      // H*W

#define LT 40        // smem row stride in halfs (32 data + 8 pad; 80B = 16B-aligned)

typedef __nv_bfloat16 bf16;

// ---------------------------------------------------------------------------
// Scratch (device globals). All T-layouts (row-major over K):
//   q,k : [B][N][CQ]   v : [B][C][N]   P : [B][N][N]
// ---------------------------------------------------------------------------
__device__ bf16 g_q[(size_t)BB * NN * CQd];            // 4 MB
__device__ bf16 g_k[(size_t)BB * NN * CQd];            // 4 MB
__device__ bf16 g_v[(size_t)BB * CC * NN];             // 16 MB
__device__ bf16 g_P[(size_t)BB * NN * NN];             // 128 MB

__device__ __forceinline__ uint32_t packbf(float a, float b) {
    __nv_bfloat162 t = __floats2bfloat162_rn(a, b);
    return *(uint32_t*)&t;
}

__device__ __forceinline__ void cp16(uint32_t dst, const void* src) {
    asm volatile("cp.async.cg.shared.global [%0], [%1], 16;" :: "r"(dst), "l"(src));
}
__device__ __forceinline__ void cp_commit() {
    asm volatile("cp.async.commit_group;" ::: "memory");
}
__device__ __forceinline__ void cp_wait0() {
    asm volatile("cp.async.wait_group 0;" ::: "memory");
}

// ---------------------------------------------------------------------------
// Warp-level compute for one 128x128x32 chunk. Both smem tiles are T-layout
// bf16 [row][LT]. 8 warps in 2(m) x 4(n); warp tile 64x32 of m16n8k16 MMAs.
//   aS/bS: byte smem addresses of tile bases.
// ---------------------------------------------------------------------------
__device__ __forceinline__ void mma_chunk(uint32_t aS, uint32_t bS,
                                          int wm, int wn, int lane,
                                          float (*acc)[4][4])
{
    const int arow = lane & 15;
    const int acol = (lane >> 4) * 8;
    const int brow = (lane & 7) + ((lane >> 4) << 3);
    const int bcol = ((lane >> 3) & 1) * 8;

    #pragma unroll
    for (int ks = 0; ks < 2; ks++) {
        const int k16 = ks * 16;
        uint32_t bfr[4][2];
        #pragma unroll
        for (int nj = 0; nj < 2; nj++) {
            uint32_t addr = bS + (uint32_t)(((wn + nj * 16 + brow) * LT) + k16 + bcol) * 2u;
            uint32_t r0, r1, r2, r3;
            asm volatile("ldmatrix.sync.aligned.m8n8.x4.shared.b16 {%0,%1,%2,%3},[%4];"
                         : "=r"(r0), "=r"(r1), "=r"(r2), "=r"(r3) : "r"(addr));
            bfr[nj * 2][0] = r0; bfr[nj * 2][1] = r1;
            bfr[nj * 2 + 1][0] = r2; bfr[nj * 2 + 1][1] = r3;
        }
        #pragma unroll
        for (int mi = 0; mi < 4; mi++) {
            uint32_t addr = aS + (uint32_t)(((wm + mi * 16 + arow) * LT) + k16 + acol) * 2u;
            uint32_t a0, a1, a2, a3;
            asm volatile("ldmatrix.sync.aligned.m8n8.x4.shared.b16 {%0,%1,%2,%3},[%4];"
                         : "=r"(a0), "=r"(a1), "=r"(a2), "=r"(a3) : "r"(addr));
            #pragma unroll
            for (int ni = 0; ni < 4; ni++) {
                asm volatile(
                    "mma.sync.aligned.m16n8k16.row.col.f32.bf16.bf16.f32 "
                    "{%0,%1,%2,%3},{%4,%5,%6,%7},{%8,%9},{%0,%1,%2,%3};"
                    : "+f"(acc[mi][ni][0]), "+f"(acc[mi][ni][1]),
                      "+f"(acc[mi][ni][2]), "+f"(acc[mi][ni][3])
                    : "r"(a0), "r"(a1), "r"(a2), "r"(a3),
                      "r"(bfr[ni][0]), "r"(bfr[ni][1]));
            }
        }
    }
}

// ---------------------------------------------------------------------------
// Main bf16 GEMM (energy / PV): both operands bf16 T-layout in gmem.
//   EPI=0 : C (bf16) = scale * acc
//   EPI=1 : C (fp32) = gamma[0] * acc + add
// 128x128 tile, BK=32, cp.async 2-stage pipeline, 256 threads.
// ---------------------------------------------------------------------------
template <int EPI>
__global__ __launch_bounds__(256)
void gemm_bf16(const bf16* __restrict__ A, const bf16* __restrict__ B,
               void* __restrict__ Cv, const float* __restrict__ add,
               const float* __restrict__ gammap,
               int K, int lda, int ldb, int ldc,
               long sA, long sB, long sC, float scale)
{
    __shared__ bf16 As[2][128 * LT];
    __shared__ bf16 Bs[2][128 * LT];

    const int b  = blockIdx.z;
    const bf16* Ab = A + (long)b * sA + (long)blockIdx.y * 128 * lda;
    const bf16* Bb = B + (long)b * sB + (long)blockIdx.x * 128 * ldb;

    const int tid  = threadIdx.x;
    const int lane = tid & 31;
    const int warp = tid >> 5;
    const int wm = (warp >> 2) * 64;
    const int wn = (warp & 3) * 32;

    const uint32_t asm0 = (uint32_t)__cvta_generic_to_shared(&As[0][0]);
    const uint32_t bsm0 = (uint32_t)__cvta_generic_to_shared(&Bs[0][0]);

    // load indices: 2 cp16 per thread per operand per chunk
    const int lr = tid >> 2;          // rows tid/4, tid/4+64
    const int lk = (tid & 3) * 8;     // 8-half group

    float acc[4][4][4];
    #pragma unroll
    for (int mi = 0; mi < 4; mi++)
        #pragma unroll
        for (int ni = 0; ni < 4; ni++)
            #pragma unroll
            for (int r = 0; r < 4; r++) acc[mi][ni][r] = 0.0f;

    const int nk = K >> 5;
    int buf = 0;

    // prologue: chunk 0
    {
        #pragma unroll
        for (int i = 0; i < 2; i++) {
            int r = lr + i * 64;
            cp16(asm0 + (uint32_t)(r * LT + lk) * 2u, Ab + (long)r * lda + lk);
            cp16(bsm0 + (uint32_t)(r * LT + lk) * 2u, Bb + (long)r * ldb + lk);
        }
        cp_commit();
    }

    for (int ki = 0; ki < nk; ki++) {
        cp_wait0();
        __syncthreads();
        if (ki + 1 < nk) {
            const int nb = buf ^ 1;
            const int k0 = (ki + 1) << 5;
            const uint32_t ao = asm0 + (uint32_t)(nb * 128 * LT) * 2u;
            const uint32_t bo = bsm0 + (uint32_t)(nb * 128 * LT) * 2u;
            #pragma unroll
            for (int i = 0; i < 2; i++) {
                int r = lr + i * 64;
                cp16(ao + (uint32_t)(r * LT + lk) * 2u, Ab + (long)r * lda + k0 + lk);
                cp16(bo + (uint32_t)(r * LT + lk) * 2u, Bb + (long)r * ldb + k0 + lk);
            }
            cp_commit();
        }
        mma_chunk(asm0 + (uint32_t)(buf * 128 * LT) * 2u,
                  bsm0 + (uint32_t)(buf * 128 * LT) * 2u,
                  wm, wn, lane, acc);
        buf ^= 1;
    }

    // epilogue
    const int g  = lane >> 2;
    const int tg = lane & 3;
    const int m0 = blockIdx.y * 128;
    const int n0 = blockIdx.x * 128;

    if (EPI == 0) {
        bf16* Cb = (bf16*)Cv + (long)b * sC;
        #pragma unroll
        for (int mi = 0; mi < 4; mi++)
            #pragma unroll
            for (int half = 0; half < 2; half++) {
                const int row = m0 + wm + mi * 16 + g + half * 8;
                #pragma unroll
                for (int ni = 0; ni < 4; ni++) {
                    const int col = n0 + wn + ni * 8 + 2 * tg;
                    uint32_t p = packbf(scale * acc[mi][ni][half * 2],
                                        scale * acc[mi][ni][half * 2 + 1]);
                    *(uint32_t*)(Cb + (long)row * ldc + col) = p;
                }
            }
    } else {
        float* Cb = (float*)Cv + (long)b * sC;
        const float gm = gammap[0];
        const float* addb = add + (long)b * sC;
        #pragma unroll
        for (int mi = 0; mi < 4; mi++)
            #pragma unroll
            for (int half = 0; half < 2; half++) {
                const int row = m0 + wm + mi * 16 + g + half * 8;
                #pragma unroll
                for (int ni = 0; ni < 4; ni++) {
                    const int col = n0 + wn + ni * 8 + 2 * tg;
                    const long off = (long)row * ldc + col;
                    float2 r = *(const float2*)&addb[off];
                    float2 v;
                    v.x = fmaf(gm, acc[mi][ni][half * 2], r.x);
                    v.y = fmaf(gm, acc[mi][ni][half * 2 + 1], r.y);
                    *(float2*)&Cb[off] = v;
                }
            }
    }
}

// ---------------------------------------------------------------------------
// Projection GEMM: fp32 sources converted to bf16 smem, bf16 output.
//   TA=true : A row-major [M][K];  TA=false : A is [K][M] (transposed on load)
//   (same for B over N)
// Single-buffered BK=32, 256 threads, same mma core.
// ---------------------------------------------------------------------------
template <bool TTA, bool TTB>
__global__ __launch_bounds__(256)
void gemm_proj(const float* __restrict__ A, const float* __restrict__ B,
               bf16* __restrict__ C,
               int K, int lda, int ldb, int ldc,
               long sA, long sB, long sC, float scale)
{
    __shared__ bf16 As[128 * LT];
    __shared__ bf16 Bs[128 * LT];

    const int b  = blockIdx.z;
    const float* Ab = A + (long)b * sA;
    const float* Bb = B + (long)b * sB;

    const int m0 = blockIdx.y * 128;
    const int n0 = blockIdx.x * 128;
    const int tid  = threadIdx.x;
    const int lane = tid & 31;
    const int warp = tid >> 5;
    const int wm = (warp >> 2) * 64;
    const int wn = (warp & 3) * 32;

    const uint32_t asm0 = (uint32_t)__cvta_generic_to_shared(&As[0]);
    const uint32_t bsm0 = (uint32_t)__cvta_generic_to_shared(&Bs[0]);

    float acc[4][4][4];
    #pragma unroll
    for (int mi = 0; mi < 4; mi++)
        #pragma unroll
        for (int ni = 0; ni < 4; ni++)
            #pragma unroll
            for (int r = 0; r < 4; r++) acc[mi][ni][r] = 0.0f;

    for (int k0 = 0; k0 < K; k0 += 32) {
        __syncthreads();
        // ---- A tile ----
        if (TTA) {
            #pragma unroll
            for (int i = 0; i < 4; i++) {
                int idx = tid + 256 * i;
                int r = idx >> 3, k4 = (idx & 7) * 4;
                float4 v = *(const float4*)&Ab[(long)(m0 + r) * lda + k0 + k4];
                uint2 p; p.x = packbf(v.x, v.y); p.y = packbf(v.z, v.w);
                *(uint2*)&As[r * LT + k4] = p;
            }
        } else {
            #pragma unroll
            for (int i = 0; i < 4; i++) {
                int idx = tid + 256 * i;
                int m = idx & 127, kq = idx >> 7;
                float x0 = Ab[(long)(k0 + kq * 4 + 0) * lda + m0 + m];
                float x1 = Ab[(long)(k0 + kq * 4 + 1) * lda + m0 + m];
                float x2 = Ab[(long)(k0 + kq * 4 + 2) * lda + m0 + m];
                float x3 = Ab[(long)(k0 + kq * 4 + 3) * lda + m0 + m];
                uint2 p; p.x = packbf(x0, x1); p.y = packbf(x2, x3);
                *(uint2*)&As[m * LT + kq * 4] = p;
            }
        }
        // ---- B tile ----
        if (TTB) {
            #pragma unroll
            for (int i = 0; i < 4; i++) {
                int idx = tid + 256 * i;
                int r = idx >> 3, k4 = (idx & 7) * 4;
                float4 v = *(const float4*)&Bb[(long)(n0 + r) * ldb + k0 + k4];
                uint2 p; p.x = packbf(v.x, v.y); p.y = packbf(v.z, v.w);
                *(uint2*)&Bs[r * LT + k4] = p;
            }
        } else {
            #pragma unroll
            for (int i = 0; i < 4; i++) {
                int idx = tid + 256 * i;
                int m = idx & 127, kq = idx >> 7;
                float x0 = Bb[(long)(k0 + kq * 4 + 0) * ldb + n0 + m];
                float x1 = Bb[(long)(k0 + kq * 4 + 1) * ldb + n0 + m];
                float x2 = Bb[(long)(k0 + kq * 4 + 2) * ldb + n0 + m];
                float x3 = Bb[(long)(k0 + kq * 4 + 3) * ldb + n0 + m];
                uint2 p; p.x = packbf(x0, x1); p.y = packbf(x2, x3);
                *(uint2*)&Bs[m * LT + kq * 4] = p;
            }
        }
        __syncthreads();
        mma_chunk(asm0, bsm0, wm, wn, lane, acc);
    }

    // epilogue: bf16 store with scale
    const int g  = lane >> 2;
    const int tg = lane & 3;
    bf16* Cb = C + (long)b * sC;
    #pragma unroll
    for (int mi = 0; mi < 4; mi++)
        #pragma unroll
        for (int half = 0; half < 2; half++) {
            const int row = m0 + wm + mi * 16 + g + half * 8;
            #pragma unroll
            for (int ni = 0; ni < 4; ni++) {
                const int col = n0 + wn + ni * 8 + 2 * tg;
                uint32_t p = packbf(scale * acc[mi][ni][half * 2],
                                    scale * acc[mi][ni][half * 2 + 1]);
                *(uint32_t*)(Cb + (long)row * ldc + col) = p;
            }
        }
}

// ---------------------------------------------------------------------------
// Row softmax over 4096 bf16, in place; fp32 internal math.
// ---------------------------------------------------------------------------
__global__ __launch_bounds__(256)
void softmax_bf16(bf16* __restrict__ P)
{
    __shared__ float buf[NN];
    __shared__ float red[8];

    const long row = blockIdx.x;
    __nv_bfloat162* p = (__nv_bfloat162*)(P + row * (long)NN);
    const int tid = threadIdx.x;

    float mx = -1e30f;
    for (int i = tid; i < NN / 2; i += 256) {
        float2 v = __bfloat1622float2(p[i]);
        *(float2*)&buf[2 * i] = v;
        mx = fmaxf(mx, fmaxf(v.x, v.y));
    }
    #pragma unroll
    for (int o = 16; o; o >>= 1) mx = fmaxf(mx, __shfl_xor_sync(0xffffffffu, mx, o));
    if ((tid & 31) == 0) red[tid >> 5] = mx;
    __syncthreads();
    if (tid == 0) {
        float v = red[0];
        #pragma unroll
        for (int i = 1; i < 8; i++) v = fmaxf(v, red[i]);
        red[0] = v;
    }
    __syncthreads();
    mx = red[0];
    __syncthreads();

    float s = 0.0f;
    for (int i = tid; i < NN; i += 256) {
        float e = __expf(buf[i] - mx);
        buf[i] = e;
        s += e;
    }
    #pragma unroll
    for (int o = 16; o; o >>= 1) s += __shfl_xor_sync(0xffffffffu, s, o);
    if ((tid & 31) == 0) red[tid >> 5] = s;
    __syncthreads();
    if (tid == 0) {
        float v = 0.0f;
        #pragma unroll
        for (int i = 0; i < 8; i++) v += red[i];
        red[0] = v;
    }
    __syncthreads();
    const float inv = 1.0f / red[0];

    for (int i = tid; i < NN / 2; i += 256) {
        p[i] = __floats2bfloat162_rn(buf[2 * i] * inv, buf[2 * i + 1] * inv);
    }
}

// ---------------------------------------------------------------------------
// Launcher
// ---------------------------------------------------------------------------
extern "C" void kernel_launch(void* const* d_in, const int* in_sizes, int n_in,
                              void* d_out, int out_size)
{
    const float* vt    = (const float*)d_in[0];
    const float* vs    = (const float*)d_in[1];
    const float* Wq    = (const float*)d_in[2];
    const float* Wk    = (const float*)d_in[3];
    const float* Wv    = (const float*)d_in[4];
    const float* gamma = (const float*)d_in[5];
    float* out = (float*)d_out;

    bf16 *qp, *kp, *vp, *Pp;
    cudaGetSymbolAddress((void**)&qp, g_q);
    cudaGetSymbolAddress((void**)&kp, g_k);
    cudaGetSymbolAddress((void**)&vp, g_v);
    cudaGetSymbolAddress((void**)&Pp, g_P);

    const float eq_scale   = 1.0f / sqrtf((float)CC);
    const float attn_scale = 1.0f / sqrtf((float)CC);

    // 1) q_t[n][o] = eq * sum_c vt[c][n] Wq[o][c]   (M=n=4096, N=o=128, K=512)
    //    A = vt [K][M] (transpose load), B = Wq [N][K] row-major
    gemm_proj<false, true><<<dim3(1, 32, BB), 256>>>(
        vt, Wq, qp, CC, NN, CC, CQd,
        (long)CC * NN, 0, (long)NN * CQd, eq_scale);

    gemm_proj<false, true><<<dim3(1, 32, BB), 256>>>(
        vs, Wk, kp, CC, NN, CC, CQd,
        (long)CC * NN, 0, (long)NN * CQd, eq_scale);

    // 2) v[c][m] = eq * sum_c' Wv[c][c'] vs[c'][m]  (M=c=512, N=m=4096, K=512)
    gemm_proj<true, false><<<dim3(32, 4, BB), 256>>>(
        Wv, vs, vp, CC, CC, NN, NN,
        0, (long)CC * NN, (long)CC * NN, eq_scale);

    // 3) energy: P[n][m] = attn * sum_o q_t[n][o] k_t[m][o]  (K=128), bf16 out
    gemm_bf16<0><<<dim3(32, 32, BB), 256>>>(
        qp, kp, Pp, nullptr, nullptr,
        CQd, CQd, CQd, NN,
        (long)NN * CQd, (long)NN * CQd, (long)NN * NN, attn_scale);

    // 4) softmax rows (bf16 in place)
    softmax_bf16<<<BB * NN, 256>>>(Pp);

    // 5) PV + residual: out[c][n] = gamma * sum_m v[c][m] P[n][m] + vt[c][n]
    gemm_bf16<1><<<dim3(32, 4, BB), 256>>>(
        vp, Pp, out, vt, gamma,
        NN, NN, NN, NN,
        (long)CC * NN, (long)NN * NN, (long)CC * NN, 1.0f);
}

// round 5
// speedup vs baseline: 5.7991x; 1.1574x over previous
#include <cuda_runtime.h>
#include <cuda_bf16.h>
#include <math.h>
#include <stdint.h>

#define BB 4
#define CC 512
#define CQd 128      // C/4
#define NN 4096      // H*W

#define LT 40        // smem row stride in halfs (32 data + 8 pad; 80B = 16B-aligned)
#define NSTAGE 3
#define STAGE_HALFS (128 * LT)
#define DSMEM_BYTES (2 * NSTAGE * STAGE_HALFS * 2)   // A+B, 3 stages, bf16

typedef __nv_bfloat16 bf16;

// ---------------------------------------------------------------------------
// Scratch (device globals). All T-layouts (row-major over K):
//   q,k : [B][N][CQ]   v : [B][C][N]   P : [B][N][N] (holds exp(E), unnormalized)
// ---------------------------------------------------------------------------
__device__ bf16  g_q[(size_t)BB * NN * CQd];            // 4 MB
__device__ bf16  g_k[(size_t)BB * NN * CQd];            // 4 MB
__device__ bf16  g_v[(size_t)BB * CC * NN];             // 16 MB
__device__ bf16  g_P[(size_t)BB * NN * NN];             // 128 MB
__device__ float g_part[(size_t)BB * NN * 32];          // 2 MB  row partial sums
__device__ float g_invS[(size_t)BB * NN];               // 64 KB 1/rowsum

__device__ __forceinline__ uint32_t packbf(float a, float b) {
    __nv_bfloat162 t = __floats2bfloat162_rn(a, b);
    return *(uint32_t*)&t;
}

__device__ __forceinline__ void cp16(uint32_t dst, const void* src) {
    asm volatile("cp.async.cg.shared.global [%0], [%1], 16;" :: "r"(dst), "l"(src));
}
__device__ __forceinline__ void cp_commit() {
    asm volatile("cp.async.commit_group;" ::: "memory");
}
__device__ __forceinline__ void cp_wait1() {
    asm volatile("cp.async.wait_group 1;" ::: "memory");
}

// ---------------------------------------------------------------------------
// Warp-level compute for one 128x128x32 chunk. Both smem tiles are T-layout
// bf16 [row][LT]. 8 warps in 2(m) x 4(n); warp tile 64x32 of m16n8k16 MMAs.
// ---------------------------------------------------------------------------
__device__ __forceinline__ void mma_chunk(uint32_t aS, uint32_t bS,
                                          int wm, int wn, int lane,
                                          float (*acc)[4][4])
{
    const int arow = lane & 15;
    const int acol = (lane >> 4) * 8;
    const int brow = (lane & 7) + ((lane >> 4) << 3);
    const int bcol = ((lane >> 3) & 1) * 8;

    #pragma unroll
    for (int ks = 0; ks < 2; ks++) {
        const int k16 = ks * 16;
        uint32_t bfr[4][2];
        #pragma unroll
        for (int nj = 0; nj < 2; nj++) {
            uint32_t addr = bS + (uint32_t)(((wn + nj * 16 + brow) * LT) + k16 + bcol) * 2u;
            uint32_t r0, r1, r2, r3;
            asm volatile("ldmatrix.sync.aligned.m8n8.x4.shared.b16 {%0,%1,%2,%3},[%4];"
                         : "=r"(r0), "=r"(r1), "=r"(r2), "=r"(r3) : "r"(addr));
            bfr[nj * 2][0] = r0; bfr[nj * 2][1] = r1;
            bfr[nj * 2 + 1][0] = r2; bfr[nj * 2 + 1][1] = r3;
        }
        #pragma unroll
        for (int mi = 0; mi < 4; mi++) {
            uint32_t addr = aS + (uint32_t)(((wm + mi * 16 + arow) * LT) + k16 + acol) * 2u;
            uint32_t a0, a1, a2, a3;
            asm volatile("ldmatrix.sync.aligned.m8n8.x4.shared.b16 {%0,%1,%2,%3},[%4];"
                         : "=r"(a0), "=r"(a1), "=r"(a2), "=r"(a3) : "r"(addr));
            #pragma unroll
            for (int ni = 0; ni < 4; ni++) {
                asm volatile(
                    "mma.sync.aligned.m16n8k16.row.col.f32.bf16.bf16.f32 "
                    "{%0,%1,%2,%3},{%4,%5,%6,%7},{%8,%9},{%0,%1,%2,%3};"
                    : "+f"(acc[mi][ni][0]), "+f"(acc[mi][ni][1]),
                      "+f"(acc[mi][ni][2]), "+f"(acc[mi][ni][3])
                    : "r"(a0), "r"(a1), "r"(a2), "r"(a3),
                      "r"(bfr[ni][0]), "r"(bfr[ni][1]));
            }
        }
    }
}

// ---------------------------------------------------------------------------
// Main bf16 GEMM (energy / PV), 128x128 tile, BK=32, 3-stage cp.async pipe.
// Tile buffers live in DYNAMIC smem (61.5 KB — above the 48 KB static limit).
//   EPI=0 (energy): C (bf16) = exp(scale*acc); emits per-row partial sums.
//   EPI=1 (PV)    : C (fp32) = gamma[0] * acc * invS[b*NN+col] + add
// ---------------------------------------------------------------------------
template <int EPI>
__global__ __launch_bounds__(256, 2)
void gemm_bf16(const bf16* __restrict__ A, const bf16* __restrict__ B,
               void* __restrict__ Cv, const float* __restrict__ add,
               const float* __restrict__ gammap,
               float* __restrict__ part, const float* __restrict__ invS,
               int K, int lda, int ldb, int ldc,
               long sA, long sB, long sC, float scale)
{
    extern __shared__ bf16 dsm[];                 // [NSTAGE][A 128*LT | B 128*LT]
    __shared__ float rowsum[128];

    const int b  = blockIdx.z;
    const bf16* Ab = A + (long)b * sA + (long)blockIdx.y * 128 * lda;
    const bf16* Bb = B + (long)b * sB + (long)blockIdx.x * 128 * ldb;

    const int tid  = threadIdx.x;
    const int lane = tid & 31;
    const int warp = tid >> 5;
    const int wm = (warp >> 2) * 64;
    const int wn = (warp & 3) * 32;

    const uint32_t asm0 = (uint32_t)__cvta_generic_to_shared(&dsm[0]);
    const uint32_t bsm0 = asm0 + (uint32_t)(NSTAGE * STAGE_HALFS) * 2u;
    const uint32_t stageB = (uint32_t)STAGE_HALFS * 2u;

    const int lr = tid >> 2;          // rows tid/4, tid/4+64
    const int lk = (tid & 3) * 8;     // 8-half group

    if (EPI == 0) {
        if (tid < 128) rowsum[tid] = 0.0f;
    }

    float acc[4][4][4];
    #pragma unroll
    for (int mi = 0; mi < 4; mi++)
        #pragma unroll
        for (int ni = 0; ni < 4; ni++)
            #pragma unroll
            for (int r = 0; r < 4; r++) acc[mi][ni][r] = 0.0f;

    const int nk = K >> 5;   // >= 4 for all our shapes

    // prologue: stages 0 and 1
    #pragma unroll
    for (int s = 0; s < 2; s++) {
        const int k0 = s << 5;
        const uint32_t ao = asm0 + s * stageB;
        const uint32_t bo = bsm0 + s * stageB;
        #pragma unroll
        for (int i = 0; i < 2; i++) {
            int r = lr + i * 64;
            cp16(ao + (uint32_t)(r * LT + lk) * 2u, Ab + (long)r * lda + k0 + lk);
            cp16(bo + (uint32_t)(r * LT + lk) * 2u, Bb + (long)r * ldb + k0 + lk);
        }
        cp_commit();
    }

    int stage = 0;
    for (int ki = 0; ki < nk; ki++) {
        cp_wait1();            // chunk ki resident; ki+1 may be in flight
        __syncthreads();
        if (ki + 2 < nk) {
            const int ns = (stage + 2 >= NSTAGE) ? (stage + 2 - NSTAGE) : (stage + 2);
            const int k0 = (ki + 2) << 5;
            const uint32_t ao = asm0 + ns * stageB;
            const uint32_t bo = bsm0 + ns * stageB;
            #pragma unroll
            for (int i = 0; i < 2; i++) {
                int r = lr + i * 64;
                cp16(ao + (uint32_t)(r * LT + lk) * 2u, Ab + (long)r * lda + k0 + lk);
                cp16(bo + (uint32_t)(r * LT + lk) * 2u, Bb + (long)r * ldb + k0 + lk);
            }
            cp_commit();
        } else {
            cp_commit();       // keep group count advancing so wait1 drains
        }
        mma_chunk(asm0 + stage * stageB, bsm0 + stage * stageB, wm, wn, lane, acc);
        stage = (stage + 1 == NSTAGE) ? 0 : stage + 1;
    }

    // epilogue
    const int g  = lane >> 2;
    const int tg = lane & 3;
    const int m0 = blockIdx.y * 128;
    const int n0 = blockIdx.x * 128;

    if (EPI == 0) {
        __syncthreads();       // rowsum zeroed + compute finished everywhere
        bf16* Cb = (bf16*)Cv + (long)b * sC;
        #pragma unroll
        for (int mi = 0; mi < 4; mi++)
            #pragma unroll
            for (int half = 0; half < 2; half++) {
                const int rl = wm + mi * 16 + g + half * 8;
                const int row = m0 + rl;
                float rs = 0.0f;
                #pragma unroll
                for (int ni = 0; ni < 4; ni++) {
                    const int col = n0 + wn + ni * 8 + 2 * tg;
                    float e0 = __expf(scale * acc[mi][ni][half * 2]);
                    float e1 = __expf(scale * acc[mi][ni][half * 2 + 1]);
                    __nv_bfloat162 t = __floats2bfloat162_rn(e0, e1);
                    *(__nv_bfloat162*)(Cb + (long)row * ldc + col) = t;
                    rs += __bfloat162float(t.x) + __bfloat162float(t.y);
                }
                atomicAdd(&rowsum[rl], rs);
            }
        __syncthreads();
        if (tid < 128)
            part[((long)b * NN + m0 + tid) * gridDim.x + blockIdx.x] = rowsum[tid];
    } else {
        float* Cb = (float*)Cv + (long)b * sC;
        const float gm = gammap[0];
        const float* addb = add + (long)b * sC;
        const float* iSb = invS + (long)b * NN;
        #pragma unroll
        for (int mi = 0; mi < 4; mi++)
            #pragma unroll
            for (int half = 0; half < 2; half++) {
                const int row = m0 + wm + mi * 16 + g + half * 8;
                #pragma unroll
                for (int ni = 0; ni < 4; ni++) {
                    const int col = n0 + wn + ni * 8 + 2 * tg;
                    const long off = (long)row * ldc + col;
                    float2 r = *(const float2*)&addb[off];
                    float2 is = *(const float2*)&iSb[col];
                    float2 v;
                    v.x = fmaf(gm * is.x, acc[mi][ni][half * 2], r.x);
                    v.y = fmaf(gm * is.y, acc[mi][ni][half * 2 + 1], r.y);
                    *(float2*)&Cb[off] = v;
                }
            }
    }
}

// ---------------------------------------------------------------------------
// Reduce 32 partials per row -> invS. One thread per row.
// ---------------------------------------------------------------------------
__global__ __launch_bounds__(256)
void reduce_rows(const float* __restrict__ part, float* __restrict__ invS)
{
    const int r = blockIdx.x * 256 + threadIdx.x;     // BB*NN rows
    const float* p = part + (long)r * 32;
    float s = 0.0f;
    #pragma unroll
    for (int i = 0; i < 32; i++) s += p[i];
    invS[r] = 1.0f / s;
}

// ---------------------------------------------------------------------------
// Projection GEMM: fp32 sources converted to bf16 smem, bf16 output.
// Single-buffered (20 KB static smem — under the limit).
// ---------------------------------------------------------------------------
template <bool TTA, bool TTB>
__global__ __launch_bounds__(256)
void gemm_proj(const float* __restrict__ A, const float* __restrict__ B,
               bf16* __restrict__ C,
               int K, int lda, int ldb, int ldc,
               long sA, long sB, long sC, float scale)
{
    __shared__ bf16 As[128 * LT];
    __shared__ bf16 Bs[128 * LT];

    const int b  = blockIdx.z;
    const float* Ab = A + (long)b * sA;
    const float* Bb = B + (long)b * sB;

    const int m0 = blockIdx.y * 128;
    const int n0 = blockIdx.x * 128;
    const int tid  = threadIdx.x;
    const int lane = tid & 31;
    const int warp = tid >> 5;
    const int wm = (warp >> 2) * 64;
    const int wn = (warp & 3) * 32;

    const uint32_t asm0 = (uint32_t)__cvta_generic_to_shared(&As[0]);
    const uint32_t bsm0 = (uint32_t)__cvta_generic_to_shared(&Bs[0]);

    float acc[4][4][4];
    #pragma unroll
    for (int mi = 0; mi < 4; mi++)
        #pragma unroll
        for (int ni = 0; ni < 4; ni++)
            #pragma unroll
            for (int r = 0; r < 4; r++) acc[mi][ni][r] = 0.0f;

    for (int k0 = 0; k0 < K; k0 += 32) {
        __syncthreads();
        if (TTA) {
            #pragma unroll
            for (int i = 0; i < 4; i++) {
                int idx = tid + 256 * i;
                int r = idx >> 3, k4 = (idx & 7) * 4;
                float4 v = *(const float4*)&Ab[(long)(m0 + r) * lda + k0 + k4];
                uint2 p; p.x = packbf(v.x, v.y); p.y = packbf(v.z, v.w);
                *(uint2*)&As[r * LT + k4] = p;
            }
        } else {
            #pragma unroll
            for (int i = 0; i < 4; i++) {
                int idx = tid + 256 * i;
                int m = idx & 127, kq = idx >> 7;
                float x0 = Ab[(long)(k0 + kq * 4 + 0) * lda + m0 + m];
                float x1 = Ab[(long)(k0 + kq * 4 + 1) * lda + m0 + m];
                float x2 = Ab[(long)(k0 + kq * 4 + 2) * lda + m0 + m];
                float x3 = Ab[(long)(k0 + kq * 4 + 3) * lda + m0 + m];
                uint2 p; p.x = packbf(x0, x1); p.y = packbf(x2, x3);
                *(uint2*)&As[m * LT + kq * 4] = p;
            }
        }
        if (TTB) {
            #pragma unroll
            for (int i = 0; i < 4; i++) {
                int idx = tid + 256 * i;
                int r = idx >> 3, k4 = (idx & 7) * 4;
                float4 v = *(const float4*)&Bb[(long)(n0 + r) * ldb + k0 + k4];
                uint2 p; p.x = packbf(v.x, v.y); p.y = packbf(v.z, v.w);
                *(uint2*)&Bs[r * LT + k4] = p;
            }
        } else {
            #pragma unroll
            for (int i = 0; i < 4; i++) {
                int idx = tid + 256 * i;
                int m = idx & 127, kq = idx >> 7;
                float x0 = Bb[(long)(k0 + kq * 4 + 0) * ldb + n0 + m];
                float x1 = Bb[(long)(k0 + kq * 4 + 1) * ldb + n0 + m];
                float x2 = Bb[(long)(k0 + kq * 4 + 2) * ldb + n0 + m];
                float x3 = Bb[(long)(k0 + kq * 4 + 3) * ldb + n0 + m];
                uint2 p; p.x = packbf(x0, x1); p.y = packbf(x2, x3);
                *(uint2*)&Bs[m * LT + kq * 4] = p;
            }
        }
        __syncthreads();
        mma_chunk(asm0, bsm0, wm, wn, lane, acc);
    }

    const int g  = lane >> 2;
    const int tg = lane & 3;
    bf16* Cb = C + (long)b * sC;
    #pragma unroll
    for (int mi = 0; mi < 4; mi++)
        #pragma unroll
        for (int half = 0; half < 2; half++) {
            const int row = m0 + wm + mi * 16 + g + half * 8;
            #pragma unroll
            for (int ni = 0; ni < 4; ni++) {
                const int col = n0 + wn + ni * 8 + 2 * tg;
                uint32_t p = packbf(scale * acc[mi][ni][half * 2],
                                    scale * acc[mi][ni][half * 2 + 1]);
                *(uint32_t*)(Cb + (long)row * ldc + col) = p;
            }
        }
}

// ---------------------------------------------------------------------------
// Launcher
// ---------------------------------------------------------------------------
extern "C" void kernel_launch(void* const* d_in, const int* in_sizes, int n_in,
                              void* d_out, int out_size)
{
    const float* vt    = (const float*)d_in[0];
    const float* vs    = (const float*)d_in[1];
    const float* Wq    = (const float*)d_in[2];
    const float* Wk    = (const float*)d_in[3];
    const float* Wv    = (const float*)d_in[4];
    const float* gamma = (const float*)d_in[5];
    float* out = (float*)d_out;

    bf16 *qp, *kp, *vp, *Pp;
    float *partp, *invSp;
    cudaGetSymbolAddress((void**)&qp, g_q);
    cudaGetSymbolAddress((void**)&kp, g_k);
    cudaGetSymbolAddress((void**)&vp, g_v);
    cudaGetSymbolAddress((void**)&Pp, g_P);
    cudaGetSymbolAddress((void**)&partp, g_part);
    cudaGetSymbolAddress((void**)&invSp, g_invS);

    static int attr_done = 0;
    if (!attr_done) {
        cudaFuncSetAttribute(gemm_bf16<0>,
                             cudaFuncAttributeMaxDynamicSharedMemorySize, DSMEM_BYTES);
        cudaFuncSetAttribute(gemm_bf16<1>,
                             cudaFuncAttributeMaxDynamicSharedMemorySize, DSMEM_BYTES);
        attr_done = 1;
    }

    const float eq_scale   = 1.0f / sqrtf((float)CC);
    const float attn_scale = 1.0f / sqrtf((float)CC);

    // 1) q_t[n][o] = eq * sum_c vt[c][n] Wq[o][c]
    gemm_proj<false, true><<<dim3(1, 32, BB), 256>>>(
        vt, Wq, qp, CC, NN, CC, CQd,
        (long)CC * NN, 0, (long)NN * CQd, eq_scale);

    gemm_proj<false, true><<<dim3(1, 32, BB), 256>>>(
        vs, Wk, kp, CC, NN, CC, CQd,
        (long)CC * NN, 0, (long)NN * CQd, eq_scale);

    // 2) v[c][m] = eq * sum_c' Wv[c][c'] vs[c'][m]
    gemm_proj<true, false><<<dim3(32, 4, BB), 256>>>(
        Wv, vs, vp, CC, CC, NN, NN,
        0, (long)CC * NN, (long)CC * NN, eq_scale);

    // 3) energy+exp: P[n][m] = exp(attn * q.k), partial row sums
    gemm_bf16<0><<<dim3(32, 32, BB), 256, DSMEM_BYTES>>>(
        qp, kp, Pp, nullptr, nullptr, partp, nullptr,
        CQd, CQd, CQd, NN,
        (long)NN * CQd, (long)NN * CQd, (long)NN * NN, attn_scale);

    // 4) invS[b][n] = 1 / sum_m P
    reduce_rows<<<(BB * NN) / 256, 256>>>(partp, invSp);

    // 5) PV + residual: out[c][n] = gamma * invS[n] * sum_m v[c][m] P[n][m] + vt[c][n]
    gemm_bf16<1><<<dim3(32, 4, BB), 256, DSMEM_BYTES>>>(
        vp, Pp, out, vt, gamma, nullptr, invSp,
        NN, NN, NN, NN,
        (long)CC * NN, (long)NN * NN, (long)CC * NN, 1.0f);
}

// round 7
// speedup vs baseline: 6.8644x; 1.1837x over previous
#include <cuda_runtime.h>
#include <cuda_bf16.h>
#include <math.h>
#include <stdint.h>

#define BB 4
#define CC 512
#define CQd 128      // C/4
#define NN 4096      // H*W

#define LTP 40       // proj smem row stride (BK=32 + 8 pad)
#define LTM 72       // main smem row stride (BK=64 + 8 pad; 144B, 16B-aligned)
#define NSTAGE 3
#define STAGE_HALFS (128 * LTM)
#define DSMEM_BYTES (2 * NSTAGE * STAGE_HALFS * 2)   // 110592 B

typedef __nv_bfloat16 bf16;

// ---------------------------------------------------------------------------
// Scratch (device globals). T-layouts:
//   q,k : [B][N][CQ]   v : [B][C][N]   P : [B][N][N] (exp(E), unnormalized)
// ---------------------------------------------------------------------------
__device__ bf16  g_q[(size_t)BB * NN * CQd];
__device__ bf16  g_k[(size_t)BB * NN * CQd];
__device__ bf16  g_v[(size_t)BB * CC * NN];
__device__ bf16  g_P[(size_t)BB * NN * NN];
__device__ float g_part[(size_t)BB * NN * 32];
__device__ float g_invS[(size_t)BB * NN];

__device__ __forceinline__ uint32_t packbf(float a, float b) {
    __nv_bfloat162 t = __floats2bfloat162_rn(a, b);
    return *(uint32_t*)&t;
}
__device__ __forceinline__ float ex2(float x) {
    float r; asm("ex2.approx.f32 %0, %1;" : "=f"(r) : "f"(x)); return r;
}
__device__ __forceinline__ void cp16(uint32_t dst, const void* src) {
    asm volatile("cp.async.cg.shared.global [%0], [%1], 16;" :: "r"(dst), "l"(src));
}
__device__ __forceinline__ void cp_commit() {
    asm volatile("cp.async.commit_group;" ::: "memory");
}
__device__ __forceinline__ void cp_wait1() {
    asm volatile("cp.async.wait_group 1;" ::: "memory");
}

// ---------------------------------------------------------------------------
// Warp compute: one 128x128xBK chunk, smem T-layout [row][LT], stride LT halfs.
// 8 warps 2(m) x 4(n); warp tile 64x32 of m16n8k16 MMAs. KSTEPS = BK/16.
// ---------------------------------------------------------------------------
template <int LT, int KSTEPS>
__device__ __forceinline__ void mma_chunk(uint32_t aS, uint32_t bS,
                                          int wm, int wn, int lane,
                                          float (*acc)[4][4])
{
    const int arow = lane & 15;
    const int acol = (lane >> 4) * 8;
    const int brow = (lane & 7) + ((lane >> 4) << 3);
    const int bcol = ((lane >> 3) & 1) * 8;

    #pragma unroll
    for (int ks = 0; ks < KSTEPS; ks++) {
        const int k16 = ks * 16;
        uint32_t bfr[4][2];
        #pragma unroll
        for (int nj = 0; nj < 2; nj++) {
            uint32_t addr = bS + (uint32_t)(((wn + nj * 16 + brow) * LT) + k16 + bcol) * 2u;
            uint32_t r0, r1, r2, r3;
            asm volatile("ldmatrix.sync.aligned.m8n8.x4.shared.b16 {%0,%1,%2,%3},[%4];"
                         : "=r"(r0), "=r"(r1), "=r"(r2), "=r"(r3) : "r"(addr));
            bfr[nj * 2][0] = r0; bfr[nj * 2][1] = r1;
            bfr[nj * 2 + 1][0] = r2; bfr[nj * 2 + 1][1] = r3;
        }
        #pragma unroll
        for (int mi = 0; mi < 4; mi++) {
            uint32_t addr = aS + (uint32_t)(((wm + mi * 16 + arow) * LT) + k16 + acol) * 2u;
            uint32_t a0, a1, a2, a3;
            asm volatile("ldmatrix.sync.aligned.m8n8.x4.shared.b16 {%0,%1,%2,%3},[%4];"
                         : "=r"(a0), "=r"(a1), "=r"(a2), "=r"(a3) : "r"(addr));
            #pragma unroll
            for (int ni = 0; ni < 4; ni++) {
                asm volatile(
                    "mma.sync.aligned.m16n8k16.row.col.f32.bf16.bf16.f32 "
                    "{%0,%1,%2,%3},{%4,%5,%6,%7},{%8,%9},{%0,%1,%2,%3};"
                    : "+f"(acc[mi][ni][0]), "+f"(acc[mi][ni][1]),
                      "+f"(acc[mi][ni][2]), "+f"(acc[mi][ni][3])
                    : "r"(a0), "r"(a1), "r"(a2), "r"(a3),
                      "r"(bfr[ni][0]), "r"(bfr[ni][1]));
            }
        }
    }
}

// ---------------------------------------------------------------------------
// Main bf16 GEMM (energy / PV), 128x128 tile, BK=64, 3-stage cp.async pipe.
//   EPI=0 (energy): C (bf16) = exp2(scale2*acc); per-row partial sums.
//   EPI=1 (PV)    : C (fp32) = gamma[0] * acc * invS[b*NN+col] + add
// Dynamic smem: 110.6 KB; 2 CTAs/SM.
// ---------------------------------------------------------------------------
template <int EPI>
__global__ __launch_bounds__(256, 2)
void gemm_main(const bf16* __restrict__ A, const bf16* __restrict__ B,
               void* __restrict__ Cv, const float* __restrict__ add,
               const float* __restrict__ gammap,
               float* __restrict__ part, const float* __restrict__ invS,
               int K, int lda, int ldb, int ldc,
               long sA, long sB, long sC, float scale)
{
    extern __shared__ bf16 dsm[];      // [NSTAGE][A 128*LTM | B 128*LTM]
    __shared__ float rowsum[128];

    const int b  = blockIdx.z;
    const bf16* Ab = A + (long)b * sA + (long)blockIdx.y * 128 * lda;
    const bf16* Bb = B + (long)b * sB + (long)blockIdx.x * 128 * ldb;

    const int tid  = threadIdx.x;
    const int lane = tid & 31;
    const int warp = tid >> 5;
    const int wm = (warp >> 2) * 64;
    const int wn = (warp & 3) * 32;

    const uint32_t asm0 = (uint32_t)__cvta_generic_to_shared(&dsm[0]);
    const uint32_t bsm0 = asm0 + (uint32_t)(NSTAGE * STAGE_HALFS) * 2u;
    const uint32_t stageB = (uint32_t)STAGE_HALFS * 2u;

    const int lr = tid >> 3;          // base row 0..31 (4 rows per thread)
    const int lk = (tid & 7) * 8;     // 8-half (16B) group within 64-half row

    if (EPI == 0) {
        if (tid < 128) rowsum[tid] = 0.0f;
    }

    float acc[4][4][4];
    #pragma unroll
    for (int mi = 0; mi < 4; mi++)
        #pragma unroll
        for (int ni = 0; ni < 4; ni++)
            #pragma unroll
            for (int r = 0; r < 4; r++) acc[mi][ni][r] = 0.0f;

    const int nk = K >> 6;   // BK=64; nk>=2 for all our shapes

    // prologue: stages 0 and 1
    #pragma unroll
    for (int s = 0; s < 2; s++) {
        const int k0 = s << 6;
        const uint32_t ao = asm0 + s * stageB;
        const uint32_t bo = bsm0 + s * stageB;
        #pragma unroll
        for (int i = 0; i < 4; i++) {
            int r = lr + i * 32;
            cp16(ao + (uint32_t)(r * LTM + lk) * 2u, Ab + (long)r * lda + k0 + lk);
            cp16(bo + (uint32_t)(r * LTM + lk) * 2u, Bb + (long)r * ldb + k0 + lk);
        }
        cp_commit();
    }

    int stage = 0;
    for (int ki = 0; ki < nk; ki++) {
        cp_wait1();            // chunk ki resident; ki+1 may be in flight
        __syncthreads();
        if (ki + 2 < nk) {
            const int ns = (stage + 2 >= NSTAGE) ? (stage + 2 - NSTAGE) : (stage + 2);
            const int k0 = (ki + 2) << 6;
            const uint32_t ao = asm0 + ns * stageB;
            const uint32_t bo = bsm0 + ns * stageB;
            #pragma unroll
            for (int i = 0; i < 4; i++) {
                int r = lr + i * 32;
                cp16(ao + (uint32_t)(r * LTM + lk) * 2u, Ab + (long)r * lda + k0 + lk);
                cp16(bo + (uint32_t)(r * LTM + lk) * 2u, Bb + (long)r * ldb + k0 + lk);
            }
            cp_commit();
        } else {
            cp_commit();       // keep group count advancing so wait1 drains
        }
        mma_chunk<LTM, 4>(asm0 + stage * stageB, bsm0 + stage * stageB, wm, wn, lane, acc);
        stage = (stage + 1 == NSTAGE) ? 0 : stage + 1;
    }

    // epilogue
    const int g  = lane >> 2;
    const int tg = lane & 3;
    const int m0 = blockIdx.y * 128;
    const int n0 = blockIdx.x * 128;

    if (EPI == 0) {
        __syncthreads();       // rowsum zeroed + compute finished everywhere
        bf16* Cb = (bf16*)Cv + (long)b * sC;
        #pragma unroll
        for (int mi = 0; mi < 4; mi++)
            #pragma unroll
            for (int half = 0; half < 2; half++) {
                const int rl = wm + mi * 16 + g + half * 8;
                const int row = m0 + rl;
                float rs = 0.0f;
                #pragma unroll
                for (int ni = 0; ni < 4; ni++) {
                    const int col = n0 + wn + ni * 8 + 2 * tg;
                    float e0 = ex2(scale * acc[mi][ni][half * 2]);
                    float e1 = ex2(scale * acc[mi][ni][half * 2 + 1]);
                    __nv_bfloat162 t = __floats2bfloat162_rn(e0, e1);
                    *(__nv_bfloat162*)(Cb + (long)row * ldc + col) = t;
                    rs += __bfloat162float(t.x) + __bfloat162float(t.y);
                }
                // reduce over the 4 threads (tg) sharing this row before one add
                rs += __shfl_xor_sync(0xffffffffu, rs, 1);
                rs += __shfl_xor_sync(0xffffffffu, rs, 2);
                if (tg == 0) atomicAdd(&rowsum[rl], rs);
            }
        __syncthreads();
        if (tid < 128)
            part[((long)b * NN + m0 + tid) * gridDim.x + blockIdx.x] = rowsum[tid];
    } else {
        float* Cb = (float*)Cv + (long)b * sC;
        const float gm = gammap[0];
        const float* addb = add + (long)b * sC;
        const float* iSb = invS + (long)b * NN;
        #pragma unroll
        for (int mi = 0; mi < 4; mi++)
            #pragma unroll
            for (int half = 0; half < 2; half++) {
                const int row = m0 + wm + mi * 16 + g + half * 8;
                #pragma unroll
                for (int ni = 0; ni < 4; ni++) {
                    const int col = n0 + wn + ni * 8 + 2 * tg;
                    const long off = (long)row * ldc + col;
                    float2 r = *(const float2*)&addb[off];
                    float2 is = *(const float2*)&iSb[col];
                    float2 v;
                    v.x = fmaf(gm * is.x, acc[mi][ni][half * 2], r.x);
                    v.y = fmaf(gm * is.y, acc[mi][ni][half * 2 + 1], r.y);
                    *(float2*)&Cb[off] = v;
                }
            }
    }
}

// ---------------------------------------------------------------------------
// Reduce 32 partials per row -> invS.
// ---------------------------------------------------------------------------
__global__ __launch_bounds__(256)
void reduce_rows(const float* __restrict__ part, float* __restrict__ invS)
{
    const int r = blockIdx.x * 256 + threadIdx.x;
    const float* p = part + (long)r * 32;
    float s = 0.0f;
    #pragma unroll
    for (int i = 0; i < 32; i++) s += p[i];
    invS[r] = 1.0f / s;
}

// ---------------------------------------------------------------------------
// Merged q/k projection: z<BB -> q from vt, else k from vs.
//   dst[n][o] = eq * sum_c X[c][n] W[o][c]
// ---------------------------------------------------------------------------
__global__ __launch_bounds__(256)
void gemm_projqk(const float* __restrict__ vt, const float* __restrict__ vs,
                 const float* __restrict__ Wq, const float* __restrict__ Wk,
                 bf16* __restrict__ qout, bf16* __restrict__ kout, float scale)
{
    __shared__ bf16 As[128 * LTP];
    __shared__ bf16 Bs[128 * LTP];

    const int z = blockIdx.z;
    const int b = (z < BB) ? z : z - BB;
    const float* Ab = ((z < BB) ? vt : vs) + (long)b * CC * NN;   // [K=CC][M=NN]
    const float* Bb = (z < BB) ? Wq : Wk;                          // [N=CQd][K=CC]
    bf16* Cb = ((z < BB) ? qout : kout) + (long)b * NN * CQd;

    const int m0 = blockIdx.y * 128;
    const int tid  = threadIdx.x;
    const int lane = tid & 31;
    const int warp = tid >> 5;
    const int wm = (warp >> 2) * 64;
    const int wn = (warp & 3) * 32;

    const uint32_t asm0 = (uint32_t)__cvta_generic_to_shared(&As[0]);
    const uint32_t bsm0 = (uint32_t)__cvta_generic_to_shared(&Bs[0]);

    float acc[4][4][4];
    #pragma unroll
    for (int mi = 0; mi < 4; mi++)
        #pragma unroll
        for (int ni = 0; ni < 4; ni++)
            #pragma unroll
            for (int r = 0; r < 4; r++) acc[mi][ni][r] = 0.0f;

    for (int k0 = 0; k0 < CC; k0 += 32) {
        __syncthreads();
        #pragma unroll
        for (int i = 0; i < 4; i++) {
            int idx = tid + 256 * i;
            int m = idx & 127, kq = idx >> 7;
            float x0 = Ab[(long)(k0 + kq * 4 + 0) * NN + m0 + m];
            float x1 = Ab[(long)(k0 + kq * 4 + 1) * NN + m0 + m];
            float x2 = Ab[(long)(k0 + kq * 4 + 2) * NN + m0 + m];
            float x3 = Ab[(long)(k0 + kq * 4 + 3) * NN + m0 + m];
            uint2 p; p.x = packbf(x0, x1); p.y = packbf(x2, x3);
            *(uint2*)&As[m * LTP + kq * 4] = p;
        }
        #pragma unroll
        for (int i = 0; i < 4; i++) {
            int idx = tid + 256 * i;
            int r = idx >> 3, k4 = (idx & 7) * 4;
            float4 v = *(const float4*)&Bb[(long)r * CC + k0 + k4];
            uint2 p; p.x = packbf(v.x, v.y); p.y = packbf(v.z, v.w);
            *(uint2*)&Bs[r * LTP + k4] = p;
        }
        __syncthreads();
        mma_chunk<LTP, 2>(asm0, bsm0, wm, wn, lane, acc);
    }

    const int g  = lane >> 2;
    const int tg = lane & 3;
    #pragma unroll
    for (int mi = 0; mi < 4; mi++)
        #pragma unroll
        for (int half = 0; half < 2; half++) {
            const int row = m0 + wm + mi * 16 + g + half * 8;
            #pragma unroll
            for (int ni = 0; ni < 4; ni++) {
                const int col = wn + ni * 8 + 2 * tg;
                uint32_t p = packbf(scale * acc[mi][ni][half * 2],
                                    scale * acc[mi][ni][half * 2 + 1]);
                *(uint32_t*)(Cb + (long)row * CQd + col) = p;
            }
        }
}

// ---------------------------------------------------------------------------
// v projection: v[c][m] = eq * sum_c' Wv[c][c'] vs[c'][m]
// ---------------------------------------------------------------------------
__global__ __launch_bounds__(256)
void gemm_projv(const float* __restrict__ Wv, const float* __restrict__ vs,
                bf16* __restrict__ vout, float scale)
{
    __shared__ bf16 As[128 * LTP];
    __shared__ bf16 Bs[128 * LTP];

    const int b  = blockIdx.z;
    const float* Bb = vs + (long)b * CC * NN;   // [K=CC][N=NN]

    const int m0 = blockIdx.y * 128;
    const int n0 = blockIdx.x * 128;
    const int tid  = threadIdx.x;
    const int lane = tid & 31;
    const int warp = tid >> 5;
    const int wm = (warp >> 2) * 64;
    const int wn = (warp & 3) * 32;

    const uint32_t asm0 = (uint32_t)__cvta_generic_to_shared(&As[0]);
    const uint32_t bsm0 = (uint32_t)__cvta_generic_to_shared(&Bs[0]);

    float acc[4][4][4];
    #pragma unroll
    for (int mi = 0; mi < 4; mi++)
        #pragma unroll
        for (int ni = 0; ni < 4; ni++)
            #pragma unroll
            for (int r = 0; r < 4; r++) acc[mi][ni][r] = 0.0f;

    for (int k0 = 0; k0 < CC; k0 += 32) {
        __syncthreads();
        #pragma unroll
        for (int i = 0; i < 4; i++) {
            int idx = tid + 256 * i;
            int r = idx >> 3, k4 = (idx & 7) * 4;
            float4 v = *(const float4*)&Wv[(long)(m0 + r) * CC + k0 + k4];
            uint2 p; p.x = packbf(v.x, v.y); p.y = packbf(v.z, v.w);
            *(uint2*)&As[r * LTP + k4] = p;
        }
        #pragma unroll
        for (int i = 0; i < 4; i++) {
            int idx = tid + 256 * i;
            int m = idx & 127, kq = idx >> 7;
            float x0 = Bb[(long)(k0 + kq * 4 + 0) * NN + n0 + m];
            float x1 = Bb[(long)(k0 + kq * 4 + 1) * NN + n0 + m];
            float x2 = Bb[(long)(k0 + kq * 4 + 2) * NN + n0 + m];
            float x3 = Bb[(long)(k0 + kq * 4 + 3) * NN + n0 + m];
            uint2 p; p.x = packbf(x0, x1); p.y = packbf(x2, x3);
            *(uint2*)&Bs[m * LTP + kq * 4] = p;
        }
        __syncthreads();
        mma_chunk<LTP, 2>(asm0, bsm0, wm, wn, lane, acc);
    }

    const int g  = lane >> 2;
    const int tg = lane & 3;
    bf16* Cb = vout + (long)b * CC * NN;
    #pragma unroll
    for (int mi = 0; mi < 4; mi++)
        #pragma unroll
        for (int half = 0; half < 2; half++) {
            const int row = m0 + wm + mi * 16 + g + half * 8;
            #pragma unroll
            for (int ni = 0; ni < 4; ni++) {
                const int col = n0 + wn + ni * 8 + 2 * tg;
                uint32_t p = packbf(scale * acc[mi][ni][half * 2],
                                    scale * acc[mi][ni][half * 2 + 1]);
                *(uint32_t*)(Cb + (long)row * NN + col) = p;
            }
        }
}

// ---------------------------------------------------------------------------
// Launcher
// ---------------------------------------------------------------------------
extern "C" void kernel_launch(void* const* d_in, const int* in_sizes, int n_in,
                              void* d_out, int out_size)
{
    const float* vt    = (const float*)d_in[0];
    const float* vs    = (const float*)d_in[1];
    const float* Wq    = (const float*)d_in[2];
    const float* Wk    = (const float*)d_in[3];
    const float* Wv    = (const float*)d_in[4];
    const float* gamma = (const float*)d_in[5];
    float* out = (float*)d_out;

    bf16 *qp, *kp, *vp, *Pp;
    float *partp, *invSp;
    cudaGetSymbolAddress((void**)&qp, g_q);
    cudaGetSymbolAddress((void**)&kp, g_k);
    cudaGetSymbolAddress((void**)&vp, g_v);
    cudaGetSymbolAddress((void**)&Pp, g_P);
    cudaGetSymbolAddress((void**)&partp, g_part);
    cudaGetSymbolAddress((void**)&invSp, g_invS);

    static int attr_done = 0;
    if (!attr_done) {
        cudaFuncSetAttribute(gemm_main<0>,
                             cudaFuncAttributeMaxDynamicSharedMemorySize, DSMEM_BYTES);
        cudaFuncSetAttribute(gemm_main<1>,
                             cudaFuncAttributeMaxDynamicSharedMemorySize, DSMEM_BYTES);
        attr_done = 1;
    }

    const float eq_scale    = 1.0f / sqrtf((float)CC);
    const float attn_scale2 = (1.0f / sqrtf((float)CC)) * 1.4426950408889634f; // *log2(e)

    // 1) q,k projections (merged)
    gemm_projqk<<<dim3(1, 32, 2 * BB), 256>>>(vt, vs, Wq, Wk, qp, kp, eq_scale);

    // 2) v projection
    gemm_projv<<<dim3(32, 4, BB), 256>>>(Wv, vs, vp, eq_scale);

    // 3) energy+exp: P[n][m] = exp2(attn_scale2 * q.k) bf16, partial row sums
    gemm_main<0><<<dim3(32, 32, BB), 256, DSMEM_BYTES>>>(
        qp, kp, Pp, nullptr, nullptr, partp, nullptr,
        CQd, CQd, CQd, NN,
        (long)NN * CQd, (long)NN * CQd, (long)NN * NN, attn_scale2);

    // 4) invS
    reduce_rows<<<(BB * NN) / 256, 256>>>(partp, invSp);

    // 5) PV + residual: out[c][n] = gamma * invS[n] * sum_m v[c][m] P[n][m] + vt[c][n]
    gemm_main<1><<<dim3(32, 4, BB), 256, DSMEM_BYTES>>>(
        vp, Pp, out, vt, gamma, nullptr, invSp,
        NN, NN, NN, NN,
        (long)CC * NN, (long)NN * NN, (long)CC * NN, 1.0f);
}